// round 1
// baseline (speedup 1.0000x reference)
#include <cuda_runtime.h>

#define N_NODES 50000
#define N_EDGES 800000
#define DIM     128
#define N_GRAPHS 64
#define N_CLASS  10
#define HID      64

// ---------------- device scratch (no dynamic allocation allowed) ----------------
__device__ float g_h[2][N_NODES * DIM];     // ping-pong node features
__device__ float g_xagg[N_NODES * DIM];     // aggregated (pre-GEMM) features
__device__ float g_ns[N_NODES];             // out_deg^-1/2
__device__ float g_nd[N_NODES];             // in_deg^-1/2
__device__ int   g_indeg[N_NODES];
__device__ int   g_outdeg[N_NODES];
__device__ int   g_rowptr[N_NODES + 1];
__device__ int   g_cursor[N_NODES];
__device__ int   g_csrsrc[N_EDGES];
__device__ float g_pooled[N_GRAPHS * DIM];
__device__ int   g_gcount[N_GRAPHS];

// ---------------- init ----------------
__global__ void zero_kernel() {
    int i = blockIdx.x * blockDim.x + threadIdx.x;
    if (i < N_NODES) { g_indeg[i] = 0; g_outdeg[i] = 0; g_cursor[i] = 0; }
    if (i < N_GRAPHS * DIM) g_pooled[i] = 0.0f;
    if (i < N_GRAPHS) g_gcount[i] = 0;
}

__global__ void degree_kernel(const int* __restrict__ src, const int* __restrict__ dst) {
    int e = blockIdx.x * blockDim.x + threadIdx.x;
    if (e < N_EDGES) {
        atomicAdd(&g_outdeg[src[e]], 1);
        atomicAdd(&g_indeg[dst[e]], 1);
    }
}

__global__ void norm_kernel() {
    int i = blockIdx.x * blockDim.x + threadIdx.x;
    if (i < N_NODES) {
        g_ns[i] = rsqrtf((float)max(g_outdeg[i], 1));
        g_nd[i] = rsqrtf((float)max(g_indeg[i], 1));
    }
}

// single-block exclusive scan of g_indeg -> g_rowptr (50000 elems)
__global__ void scan_kernel() {
    __shared__ int ssum[1024];
    const int CH = 49; // 1024*49 = 50176 >= 50000
    int t = threadIdx.x;
    int start = t * CH;
    int local = 0;
    for (int i = 0; i < CH; i++) {
        int idx = start + i;
        if (idx < N_NODES) local += g_indeg[idx];
    }
    ssum[t] = local;
    __syncthreads();
    // Hillis-Steele inclusive scan
    for (int off = 1; off < 1024; off <<= 1) {
        int v = (t >= off) ? ssum[t - off] : 0;
        __syncthreads();
        ssum[t] += v;
        __syncthreads();
    }
    int run = (t == 0) ? 0 : ssum[t - 1];
    for (int i = 0; i < CH; i++) {
        int idx = start + i;
        if (idx < N_NODES) {
            g_rowptr[idx] = run;
            run += g_indeg[idx];
            if (idx == N_NODES - 1) g_rowptr[N_NODES] = run;
        }
    }
}

__global__ void fill_csr(const int* __restrict__ src, const int* __restrict__ dst) {
    int e = blockIdx.x * blockDim.x + threadIdx.x;
    if (e < N_EDGES) {
        int v = dst[e];
        int ofs = atomicAdd(&g_cursor[v], 1);
        g_csrsrc[g_rowptr[v] + ofs] = src[e];
    }
}

// ---------------- aggregation: one warp per destination node ----------------
// out[v] = (use_norm ? nd[v] : 1) * sum_{e: dst=v} (use_norm ? ns[src] : 1) * hin[src]
__global__ void aggregate_kernel(const float* __restrict__ hin_ext, int hin_buf,
                                 float* __restrict__ out_ext, int use_norm) {
    const float* hin = hin_ext ? hin_ext : g_h[hin_buf];
    float* out = out_ext ? out_ext : g_xagg;

    int warp = (blockIdx.x * blockDim.x + threadIdx.x) >> 5;
    if (warp >= N_NODES) return;
    int lane = threadIdx.x & 31;

    int beg = g_rowptr[warp];
    int end = g_rowptr[warp + 1];

    const float4* h4 = (const float4*)hin;
    float4 acc = make_float4(0.f, 0.f, 0.f, 0.f);

    for (int i = beg; i < end; i++) {
        int s = g_csrsrc[i];
        float w = use_norm ? g_ns[s] : 1.0f;
        float4 v = h4[s * 32 + lane];
        acc.x += w * v.x;
        acc.y += w * v.y;
        acc.z += w * v.z;
        acc.w += w * v.w;
    }
    float sc = use_norm ? g_nd[warp] : 1.0f;
    acc.x *= sc; acc.y *= sc; acc.z *= sc; acc.w *= sc;
    ((float4*)out)[warp * 32 + lane] = acc;
}

// ---------------- fused GEMM + bias + relu: g_h[out_buf] = relu(g_xagg @ W + b) ----------------
// A: [N,128], W: [128,128] row-major (in,out), BM=64, BN=128, BK=32, thread tile 4x8
__global__ void gemm_bias_relu(const float* __restrict__ W, const float* __restrict__ b,
                               int out_buf) {
    __shared__ float sA[64][33];
    __shared__ float sW[32][128];

    const float* A = g_xagg;
    float* C = g_h[out_buf];

    int block_row = blockIdx.x * 64;
    int tx = threadIdx.x % 16;       // 16 col groups of 8
    int ty = threadIdx.x / 16;       // 16 row groups of 4

    float acc[4][8];
#pragma unroll
    for (int r = 0; r < 4; r++)
#pragma unroll
        for (int c = 0; c < 8; c++) acc[r][c] = 0.f;

    for (int k0 = 0; k0 < 128; k0 += 32) {
        // load A tile 64x32
        for (int i = threadIdx.x; i < 64 * 32; i += 256) {
            int r = i / 32, c = i % 32;
            int row = block_row + r;
            sA[r][c] = (row < N_NODES) ? A[row * 128 + k0 + c] : 0.f;
        }
        // load W tile 32x128
        for (int i = threadIdx.x; i < 32 * 128; i += 256) {
            int r = i / 128, c = i % 128;
            sW[r][c] = W[(k0 + r) * 128 + c];
        }
        __syncthreads();

#pragma unroll
        for (int kk = 0; kk < 32; kk++) {
            float a[4];
#pragma unroll
            for (int r = 0; r < 4; r++) a[r] = sA[ty * 4 + r][kk];
            float4 w0 = *(const float4*)&sW[kk][tx * 8];
            float4 w1 = *(const float4*)&sW[kk][tx * 8 + 4];
            float wv[8] = {w0.x, w0.y, w0.z, w0.w, w1.x, w1.y, w1.z, w1.w};
#pragma unroll
            for (int r = 0; r < 4; r++)
#pragma unroll
                for (int c = 0; c < 8; c++) acc[r][c] += a[r] * wv[c];
        }
        __syncthreads();
    }

#pragma unroll
    for (int r = 0; r < 4; r++) {
        int row = block_row + ty * 4 + r;
        if (row < N_NODES) {
#pragma unroll
            for (int c = 0; c < 8; c++) {
                int col = tx * 8 + c;
                float v = acc[r][c] + b[col];
                v = fmaxf(v, 0.0f);
                C[row * 128 + col] = v;
            }
        }
    }
}

// ---------------- per-graph pooling (atomic accumulate) ----------------
__global__ void pool_kernel(int buf, const int* __restrict__ gid) {
    int tid = blockIdx.x * blockDim.x + threadIdx.x;
    int node = tid >> 5;
    if (node >= N_NODES) return;
    int lane = tid & 31;
    int g = gid[node];
    float4 v = ((const float4*)g_h[buf])[node * 32 + lane];
    float* p = &g_pooled[g * 128 + lane * 4];
    atomicAdd(p + 0, v.x);
    atomicAdd(p + 1, v.y);
    atomicAdd(p + 2, v.z);
    atomicAdd(p + 3, v.w);
    if (lane == 0) atomicAdd(&g_gcount[g], 1);
}

// ---------------- head MLP: scores = relu(mean_pool @ Wa + ba) @ Wb + bb ----------------
__global__ void mlp_kernel(const float* __restrict__ Wa, const float* __restrict__ ba,
                           const float* __restrict__ Wb, const float* __restrict__ bb,
                           float* __restrict__ out) {
    __shared__ float pm[N_GRAPHS * DIM];   // 32KB
    __shared__ float z[N_GRAPHS * HID];    // 16KB
    int t = threadIdx.x;

    for (int i = t; i < N_GRAPHS * DIM; i += 256) {
        int g = i / DIM;
        float cnt = fmaxf((float)g_gcount[g], 1.0f);
        pm[i] = g_pooled[i] / cnt;
    }
    __syncthreads();

    for (int i = t; i < N_GRAPHS * HID; i += 256) {
        int g = i / HID, j = i % HID;
        float s = ba[j];
        for (int d = 0; d < DIM; d++) s += pm[g * DIM + d] * Wa[d * HID + j];
        z[i] = fmaxf(s, 0.0f);
    }
    __syncthreads();

    for (int i = t; i < N_GRAPHS * N_CLASS; i += 256) {
        int g = i / N_CLASS, c = i % N_CLASS;
        float s = bb[c];
        for (int j = 0; j < HID; j++) s += z[g * HID + j] * Wb[j * N_CLASS + c];
        out[i] = s;
    }
}

// ---------------- launch ----------------
extern "C" void kernel_launch(void* const* d_in, const int* in_sizes, int n_in,
                              void* d_out, int out_size) {
    const float* feat = (const float*)d_in[0];
    const int* src = (const int*)d_in[1];
    const int* dst = (const int*)d_in[2];
    const int* gid = (const int*)d_in[3];
    const float* Ws[6] = {(const float*)d_in[4], (const float*)d_in[6], (const float*)d_in[8],
                          (const float*)d_in[10], (const float*)d_in[12], (const float*)d_in[14]};
    const float* bs[6] = {(const float*)d_in[5], (const float*)d_in[7], (const float*)d_in[9],
                          (const float*)d_in[11], (const float*)d_in[13], (const float*)d_in[15]};
    const float* Wa = (const float*)d_in[16];
    const float* ba = (const float*)d_in[17];
    const float* Wb = (const float*)d_in[18];
    const float* bb = (const float*)d_in[19];
    float* out = (float*)d_out;

    // graph structure
    zero_kernel<<<(N_NODES + 255) / 256, 256>>>();
    degree_kernel<<<(N_EDGES + 255) / 256, 256>>>(src, dst);
    norm_kernel<<<(N_NODES + 255) / 256, 256>>>();
    scan_kernel<<<1, 1024>>>();
    fill_csr<<<(N_EDGES + 255) / 256, 256>>>(src, dst);

    const int AGG_GRID = (N_NODES * 32 + 255) / 256;   // one warp per node
    const int GEMM_GRID = (N_NODES + 63) / 64;

    // 6 GraphConv layers
    for (int L = 0; L < 6; L++) {
        const float* hin_ext = (L == 0) ? feat : nullptr;
        int hin_buf = (L == 0) ? 0 : ((L - 1) & 1);
        aggregate_kernel<<<AGG_GRID, 256>>>(hin_ext, hin_buf, nullptr, 1);
        gemm_bias_relu<<<GEMM_GRID, 256>>>(Ws[L], bs[L], L & 1);
    }
    int final_buf = 5 & 1; // = 1

    // per-graph mean pool + head MLP -> scores [64,10] at out[0..639]
    pool_kernel<<<AGG_GRID, 256>>>(final_buf, gid);
    mlp_kernel<<<1, 256>>>(Wa, ba, Wb, bb, out);

    // unnormalized aggregation h_agg [50000,128] at out[640..]
    aggregate_kernel<<<AGG_GRID, 256>>>(nullptr, final_buf, out + N_GRAPHS * N_CLASS, 0);
}

// round 3
// speedup vs baseline: 1.7101x; 1.7101x over previous
#include <cuda_runtime.h>

#define N_NODES 50000
#define N_EDGES 800000
#define DIM     128
#define N_GRAPHS 64
#define N_CLASS  10
#define HID      64
#define SCAN_BLOCKS 196   // ceil(50000/256)

// ---------------- device scratch ----------------
__device__ float g_h[2][N_NODES * DIM];
__device__ float g_xagg[N_NODES * DIM];
__device__ float g_ns[N_NODES];
__device__ float g_nd[N_NODES];
__device__ int   g_indeg[N_NODES];
__device__ int   g_outdeg[N_NODES];
__device__ int   g_rowptr[N_NODES + 1];
__device__ int   g_cursor[N_NODES];
__device__ int   g_csrsrc[N_EDGES];
__device__ float g_pooled[N_GRAPHS * DIM];
__device__ int   g_gcount[N_GRAPHS];
__device__ int   g_blksum[256];
__device__ int   g_blkoff[256];

// ---------------- init ----------------
__global__ void zero_kernel() {
    int i = blockIdx.x * blockDim.x + threadIdx.x;
    if (i < N_NODES) { g_indeg[i] = 0; g_outdeg[i] = 0; g_cursor[i] = 0; }
    if (i < N_GRAPHS * DIM) g_pooled[i] = 0.0f;
    if (i < N_GRAPHS) g_gcount[i] = 0;
}

__global__ void degree_kernel(const int* __restrict__ src, const int* __restrict__ dst) {
    int e = blockIdx.x * blockDim.x + threadIdx.x;
    if (e < N_EDGES) {
        atomicAdd(&g_outdeg[src[e]], 1);
        atomicAdd(&g_indeg[dst[e]], 1);
    }
}

__global__ void norm_kernel() {
    int i = blockIdx.x * blockDim.x + threadIdx.x;
    if (i < N_NODES) {
        g_ns[i] = rsqrtf((float)max(g_outdeg[i], 1));
        g_nd[i] = rsqrtf((float)max(g_indeg[i], 1));
    }
}

// ---------------- 3-phase parallel scan of g_indeg -> g_rowptr ----------------
__global__ void scan_part1() {
    int i = blockIdx.x * 256 + threadIdx.x;
    int v = (i < N_NODES) ? g_indeg[i] : 0;
#pragma unroll
    for (int o = 16; o; o >>= 1) v += __shfl_down_sync(0xffffffffu, v, o);
    __shared__ int ws[8];
    if ((threadIdx.x & 31) == 0) ws[threadIdx.x >> 5] = v;
    __syncthreads();
    if (threadIdx.x < 8) {
        int s = ws[threadIdx.x];
#pragma unroll
        for (int o = 4; o; o >>= 1) s += __shfl_down_sync(0xffu, s, o);
        if (threadIdx.x == 0) g_blksum[blockIdx.x] = s;
    }
}

__global__ void scan_part2() {
    __shared__ int s[256];
    int t = threadIdx.x;
    int v = (t < SCAN_BLOCKS) ? g_blksum[t] : 0;
    s[t] = v;
    __syncthreads();
    for (int o = 1; o < 256; o <<= 1) {
        int x = (t >= o) ? s[t - o] : 0;
        __syncthreads();
        s[t] += x;
        __syncthreads();
    }
    if (t < SCAN_BLOCKS) g_blkoff[t] = s[t] - v;
}

__global__ void scan_part3() {
    __shared__ int s[256];
    int t = threadIdx.x;
    int i = blockIdx.x * 256 + t;
    int v = (i < N_NODES) ? g_indeg[i] : 0;
    s[t] = v;
    __syncthreads();
    for (int o = 1; o < 256; o <<= 1) {
        int x = (t >= o) ? s[t - o] : 0;
        __syncthreads();
        s[t] += x;
        __syncthreads();
    }
    if (i < N_NODES) {
        int r = g_blkoff[blockIdx.x] + s[t] - v;
        g_rowptr[i] = r;
        if (i == N_NODES - 1) g_rowptr[N_NODES] = r + v;
    }
}

__global__ void fill_csr(const int* __restrict__ src, const int* __restrict__ dst) {
    int e = blockIdx.x * blockDim.x + threadIdx.x;
    if (e < N_EDGES) {
        int v = dst[e];
        int ofs = atomicAdd(&g_cursor[v], 1);
        g_csrsrc[g_rowptr[v] + ofs] = src[e];
    }
}

// ---------------- aggregation: one warp per destination node, 4x unrolled ----------------
// Buffer selection happens IN DEVICE CODE (never pass __device__ symbols from host).
// in_sel: 0 -> g_h[0], 1 -> g_h[1], -1 -> ext_in
// out_sel: 2 -> g_xagg, -1 -> ext_out
template <int SRC_NORM, int DST_NORM>
__global__ void aggregate_kernel(const float* __restrict__ ext_in, int in_sel,
                                 float* __restrict__ ext_out, int out_sel) {
    const float* hin = (in_sel == 0) ? g_h[0] : (in_sel == 1) ? g_h[1] : ext_in;
    float* out = (out_sel == 2) ? g_xagg : ext_out;

    int warp = (blockIdx.x * blockDim.x + threadIdx.x) >> 5;
    if (warp >= N_NODES) return;
    int lane = threadIdx.x & 31;

    int beg = g_rowptr[warp];
    int end = g_rowptr[warp + 1];

    const float4* h4 = (const float4*)hin;
    float4 acc = make_float4(0.f, 0.f, 0.f, 0.f);

    int i = beg;
    for (; i + 4 <= end; i += 4) {
        int s0 = g_csrsrc[i + 0];
        int s1 = g_csrsrc[i + 1];
        int s2 = g_csrsrc[i + 2];
        int s3 = g_csrsrc[i + 3];
        float w0 = SRC_NORM ? g_ns[s0] : 1.0f;
        float w1 = SRC_NORM ? g_ns[s1] : 1.0f;
        float w2 = SRC_NORM ? g_ns[s2] : 1.0f;
        float w3 = SRC_NORM ? g_ns[s3] : 1.0f;
        float4 v0 = h4[s0 * 32 + lane];
        float4 v1 = h4[s1 * 32 + lane];
        float4 v2 = h4[s2 * 32 + lane];
        float4 v3 = h4[s3 * 32 + lane];
        acc.x += w0 * v0.x; acc.y += w0 * v0.y; acc.z += w0 * v0.z; acc.w += w0 * v0.w;
        acc.x += w1 * v1.x; acc.y += w1 * v1.y; acc.z += w1 * v1.z; acc.w += w1 * v1.w;
        acc.x += w2 * v2.x; acc.y += w2 * v2.y; acc.z += w2 * v2.z; acc.w += w2 * v2.w;
        acc.x += w3 * v3.x; acc.y += w3 * v3.y; acc.z += w3 * v3.z; acc.w += w3 * v3.w;
    }
    for (; i < end; i++) {
        int s = g_csrsrc[i];
        float w = SRC_NORM ? g_ns[s] : 1.0f;
        float4 v = h4[s * 32 + lane];
        acc.x += w * v.x; acc.y += w * v.y; acc.z += w * v.z; acc.w += w * v.w;
    }
    if (DST_NORM) {
        float sc = g_nd[warp];
        acc.x *= sc; acc.y *= sc; acc.z *= sc; acc.w *= sc;
    }
    ((float4*)out)[warp * 32 + lane] = acc;
}

// ---------------- GEMM + bias + relu (+ optional postscale by g_ns) ----------------
// g_h[out_buf][row] = relu(g_xagg[row] @ W + b) * (do_ps ? g_ns[row] : 1)
// BM=128, BN=128, BK=32, 256 threads, 8x8 micro-tile
__global__ void __launch_bounds__(256) gemm_bias_relu(
    const float* __restrict__ W, const float* __restrict__ b,
    int out_buf, int do_ps) {
    __shared__ float sA[128][33];
    __shared__ float sW[32][128];

    const float* A = g_xagg;
    float* C = g_h[out_buf];

    int block_row = blockIdx.x * 128;
    int tid = threadIdx.x;
    int tx = tid % 16;  // n-group (8 cols each)
    int ty = tid / 16;  // m-group (8 rows each)

    float acc[8][8];
#pragma unroll
    for (int r = 0; r < 8; r++)
#pragma unroll
        for (int c = 0; c < 8; c++) acc[r][c] = 0.f;

    const float4* A4 = (const float4*)A;
    const float4* W4 = (const float4*)W;

    for (int k0 = 0; k0 < 128; k0 += 32) {
        // load A tile 128x32 (1024 float4)
#pragma unroll
        for (int j = 0; j < 4; j++) {
            int f = tid + 256 * j;
            int r = f >> 3, c4 = f & 7;
            int row = block_row + r;
            float4 v = (row < N_NODES) ? A4[row * 32 + (k0 >> 2) + c4]
                                       : make_float4(0.f, 0.f, 0.f, 0.f);
            sA[r][c4 * 4 + 0] = v.x; sA[r][c4 * 4 + 1] = v.y;
            sA[r][c4 * 4 + 2] = v.z; sA[r][c4 * 4 + 3] = v.w;
        }
        // load W tile 32x128 (1024 float4)
#pragma unroll
        for (int j = 0; j < 4; j++) {
            int f = tid + 256 * j;
            int r = f >> 5, c4 = f & 31;
            float4 v = W4[(k0 + r) * 32 + c4];
            *(float4*)&sW[r][c4 * 4] = v;
        }
        __syncthreads();

#pragma unroll 8
        for (int kk = 0; kk < 32; kk++) {
            float a[8];
#pragma unroll
            for (int r = 0; r < 8; r++) a[r] = sA[ty * 8 + r][kk];
            float4 w0 = *(const float4*)&sW[kk][tx * 8];
            float4 w1 = *(const float4*)&sW[kk][tx * 8 + 4];
            float wv[8] = {w0.x, w0.y, w0.z, w0.w, w1.x, w1.y, w1.z, w1.w};
#pragma unroll
            for (int r = 0; r < 8; r++)
#pragma unroll
                for (int c = 0; c < 8; c++) acc[r][c] += a[r] * wv[c];
        }
        __syncthreads();
    }

    float4 b0 = *(const float4*)&b[tx * 8];
    float4 b1 = *(const float4*)&b[tx * 8 + 4];
    float bv[8] = {b0.x, b0.y, b0.z, b0.w, b1.x, b1.y, b1.z, b1.w};

#pragma unroll
    for (int r = 0; r < 8; r++) {
        int row = block_row + ty * 8 + r;
        if (row < N_NODES) {
            float ps = do_ps ? g_ns[row] : 1.0f;
            float o[8];
#pragma unroll
            for (int c = 0; c < 8; c++) o[c] = fmaxf(acc[r][c] + bv[c], 0.f) * ps;
            *(float4*)&C[row * 128 + tx * 8] = make_float4(o[0], o[1], o[2], o[3]);
            *(float4*)&C[row * 128 + tx * 8 + 4] = make_float4(o[4], o[5], o[6], o[7]);
        }
    }
}

// ---------------- pooling: sorted graph_id -> register accumulation, few atomics ----------------
// block = 256 threads = 2 groups of 128; each group handles 128 contiguous nodes.
__global__ void pool_kernel(int buf, const int* __restrict__ gid) {
    const float* h = g_h[buf];
    int group = blockIdx.x * 2 + (threadIdx.x >> 7);
    int d = threadIdx.x & 127;
    int start = group * 128;
    if (start >= N_NODES) return;
    int end = min(start + 128, N_NODES);

    int cur = gid[start];
    float acc = 0.f;
    int cnt = 0;
    for (int n = start; n < end; n++) {
        int g = gid[n];
        if (g != cur) {
            atomicAdd(&g_pooled[cur * DIM + d], acc);
            if (d == 0) atomicAdd(&g_gcount[cur], cnt);
            acc = 0.f; cnt = 0; cur = g;
        }
        acc += h[n * DIM + d];
        cnt++;
    }
    atomicAdd(&g_pooled[cur * DIM + d], acc);
    if (d == 0) atomicAdd(&g_gcount[cur], cnt);
}

// ---------------- head MLP ----------------
__global__ void mlp_kernel(const float* __restrict__ Wa, const float* __restrict__ ba,
                           const float* __restrict__ Wb, const float* __restrict__ bb,
                           float* __restrict__ out) {
    __shared__ float pm[N_GRAPHS * DIM];
    __shared__ float z[N_GRAPHS * HID];
    int t = threadIdx.x;

    for (int i = t; i < N_GRAPHS * DIM; i += 256) {
        int g = i / DIM;
        float cnt = fmaxf((float)g_gcount[g], 1.0f);
        pm[i] = g_pooled[i] / cnt;
    }
    __syncthreads();

    for (int i = t; i < N_GRAPHS * HID; i += 256) {
        int g = i / HID, j = i % HID;
        float s = ba[j];
        for (int d = 0; d < DIM; d++) s += pm[g * DIM + d] * Wa[d * HID + j];
        z[i] = fmaxf(s, 0.0f);
    }
    __syncthreads();

    for (int i = t; i < N_GRAPHS * N_CLASS; i += 256) {
        int g = i / N_CLASS, c = i % N_CLASS;
        float s = bb[c];
        for (int j = 0; j < HID; j++) s += z[g * HID + j] * Wb[j * N_CLASS + c];
        out[i] = s;
    }
}

// ---------------- launch ----------------
extern "C" void kernel_launch(void* const* d_in, const int* in_sizes, int n_in,
                              void* d_out, int out_size) {
    const float* feat = (const float*)d_in[0];
    const int* src = (const int*)d_in[1];
    const int* dst = (const int*)d_in[2];
    const int* gid = (const int*)d_in[3];
    const float* Ws[6] = {(const float*)d_in[4], (const float*)d_in[6], (const float*)d_in[8],
                          (const float*)d_in[10], (const float*)d_in[12], (const float*)d_in[14]};
    const float* bs[6] = {(const float*)d_in[5], (const float*)d_in[7], (const float*)d_in[9],
                          (const float*)d_in[11], (const float*)d_in[13], (const float*)d_in[15]};
    const float* Wa = (const float*)d_in[16];
    const float* ba = (const float*)d_in[17];
    const float* Wb = (const float*)d_in[18];
    const float* bb = (const float*)d_in[19];
    float* out = (float*)d_out;

    // graph structure
    zero_kernel<<<SCAN_BLOCKS, 256>>>();
    degree_kernel<<<(N_EDGES + 255) / 256, 256>>>(src, dst);
    norm_kernel<<<SCAN_BLOCKS, 256>>>();
    scan_part1<<<SCAN_BLOCKS, 256>>>();
    scan_part2<<<1, 256>>>();
    scan_part3<<<SCAN_BLOCKS, 256>>>();
    fill_csr<<<(N_EDGES + 255) / 256, 256>>>(src, dst);

    const int AGG_GRID = (N_NODES * 32 + 255) / 256;   // one warp per node
    const int GEMM_GRID = (N_NODES + 127) / 128;

    // Layer 0: input feat unscaled -> per-edge src norm in aggregation.
    // GEMM epilogue pre-scales layers 0..4 output by ns, so layers 1..5
    // aggregate WITHOUT per-edge src-norm loads. relu(x)*ns == relu(x*ns), ns>0.
    aggregate_kernel<1, 1><<<AGG_GRID, 256>>>(feat, -1, nullptr, 2);
    gemm_bias_relu<<<GEMM_GRID, 256>>>(Ws[0], bs[0], 0, 1);

    for (int L = 1; L < 6; L++) {
        aggregate_kernel<0, 1><<<AGG_GRID, 256>>>(nullptr, (L - 1) & 1, nullptr, 2);
        gemm_bias_relu<<<GEMM_GRID, 256>>>(Ws[L], bs[L], L & 1, (L < 5) ? 1 : 0);
    }
    // final features live in g_h[1]

    // per-graph mean pool + head MLP -> scores [64,10]
    pool_kernel<<<SCAN_BLOCKS, 256>>>(1, gid);
    mlp_kernel<<<1, 256>>>(Wa, ba, Wb, bb, out);

    // unnormalized aggregation h_agg [50000,128]
    aggregate_kernel<0, 0><<<AGG_GRID, 256>>>(nullptr, 1, out + N_GRAPHS * N_CLASS, -1);
}

// round 5
// speedup vs baseline: 2.1713x; 1.2697x over previous
#include <cuda_runtime.h>
#include <cuda_bf16.h>
#include <cstdint>

#define N_NODES 50000
#define N_EDGES 800000
#define DIM     128
#define N_GRAPHS 64
#define N_CLASS  10
#define HID      64
#define SCAN_BLOCKS 196   // ceil(50000/256)
#define N_TILES 391       // ceil(50000/128)
#define N_PAD   (N_TILES * 128)
#define SA      136       // padded K-stride in smem (bank-conflict-free fragments)

// ---------------- device scratch ----------------
__device__ float g_h[2][N_NODES * DIM];
__device__ unsigned short g_Ahi[N_PAD * DIM];   // row-major bf16 hi of aggregated feats
__device__ unsigned short g_Alo[N_PAD * DIM];   // row-major bf16 lo
__device__ unsigned short g_Whi[6 * DIM * DIM]; // row-major W^T [N][K] bf16 hi
__device__ unsigned short g_Wlo[6 * DIM * DIM];
__device__ float g_ns[N_NODES];
__device__ float g_nd[N_NODES];
__device__ int   g_indeg[N_NODES];
__device__ int   g_outdeg[N_NODES];
__device__ int   g_rowptr[N_NODES + 1];
__device__ int   g_cursor[N_NODES];
__device__ int   g_csrsrc[N_EDGES];
__device__ float g_pooled[N_GRAPHS * DIM];
__device__ int   g_gcount[N_GRAPHS];
__device__ int   g_blksum[256];
__device__ int   g_blkoff[256];

__device__ __forceinline__ void split_bf(float x, unsigned short& hi, unsigned short& lo) {
    __nv_bfloat16 h = __float2bfloat16_rn(x);
    hi = __bfloat16_as_ushort(h);
    lo = __bfloat16_as_ushort(__float2bfloat16_rn(x - __bfloat162float(h)));
}

__device__ __forceinline__ void mma16816(float* c, const uint32_t* a, const uint32_t* b) {
    asm volatile(
        "mma.sync.aligned.m16n8k16.row.col.f32.bf16.bf16.f32 "
        "{%0,%1,%2,%3}, {%4,%5,%6,%7}, {%8,%9}, {%0,%1,%2,%3};"
        : "+f"(c[0]), "+f"(c[1]), "+f"(c[2]), "+f"(c[3])
        : "r"(a[0]), "r"(a[1]), "r"(a[2]), "r"(a[3]), "r"(b[0]), "r"(b[1]));
}

// ---------------- init ----------------
__global__ void zero_kernel() {
    int i = blockIdx.x * blockDim.x + threadIdx.x;
    if (i < N_NODES) { g_indeg[i] = 0; g_outdeg[i] = 0; g_cursor[i] = 0; }
    if (i < N_GRAPHS * DIM) g_pooled[i] = 0.0f;
    if (i < N_GRAPHS) g_gcount[i] = 0;
    // zero padded tail rows (50000..50047) once; they never get written again
    if (i < 768) ((uint4*)(g_Ahi + N_NODES * DIM))[i] = make_uint4(0, 0, 0, 0);
    else if (i < 1536) ((uint4*)(g_Alo + N_NODES * DIM))[i - 768] = make_uint4(0, 0, 0, 0);
}

__global__ void degree_kernel(const int* __restrict__ src, const int* __restrict__ dst) {
    int e = blockIdx.x * blockDim.x + threadIdx.x;
    if (e < N_EDGES) {
        atomicAdd(&g_outdeg[src[e]], 1);
        atomicAdd(&g_indeg[dst[e]], 1);
    }
}

__global__ void norm_kernel() {
    int i = blockIdx.x * blockDim.x + threadIdx.x;
    if (i < N_NODES) {
        g_ns[i] = rsqrtf((float)max(g_outdeg[i], 1));
        g_nd[i] = rsqrtf((float)max(g_indeg[i], 1));
    }
}

// ---------------- 3-phase parallel scan of g_indeg -> g_rowptr ----------------
__global__ void scan_part1() {
    int i = blockIdx.x * 256 + threadIdx.x;
    int v = (i < N_NODES) ? g_indeg[i] : 0;
#pragma unroll
    for (int o = 16; o; o >>= 1) v += __shfl_down_sync(0xffffffffu, v, o);
    __shared__ int ws[8];
    if ((threadIdx.x & 31) == 0) ws[threadIdx.x >> 5] = v;
    __syncthreads();
    if (threadIdx.x < 8) {
        int s = ws[threadIdx.x];
#pragma unroll
        for (int o = 4; o; o >>= 1) s += __shfl_down_sync(0xffu, s, o);
        if (threadIdx.x == 0) g_blksum[blockIdx.x] = s;
    }
}

__global__ void scan_part2() {
    __shared__ int s[256];
    int t = threadIdx.x;
    int v = (t < SCAN_BLOCKS) ? g_blksum[t] : 0;
    s[t] = v;
    __syncthreads();
    for (int o = 1; o < 256; o <<= 1) {
        int x = (t >= o) ? s[t - o] : 0;
        __syncthreads();
        s[t] += x;
        __syncthreads();
    }
    if (t < SCAN_BLOCKS) g_blkoff[t] = s[t] - v;
}

__global__ void scan_part3() {
    __shared__ int s[256];
    int t = threadIdx.x;
    int i = blockIdx.x * 256 + t;
    int v = (i < N_NODES) ? g_indeg[i] : 0;
    s[t] = v;
    __syncthreads();
    for (int o = 1; o < 256; o <<= 1) {
        int x = (t >= o) ? s[t - o] : 0;
        __syncthreads();
        s[t] += x;
        __syncthreads();
    }
    if (i < N_NODES) {
        int r = g_blkoff[blockIdx.x] + s[t] - v;
        g_rowptr[i] = r;
        if (i == N_NODES - 1) g_rowptr[N_NODES] = r + v;
    }
}

__global__ void fill_csr(const int* __restrict__ src, const int* __restrict__ dst) {
    int e = blockIdx.x * blockDim.x + threadIdx.x;
    if (e < N_EDGES) {
        int v = dst[e];
        int ofs = atomicAdd(&g_cursor[v], 1);
        g_csrsrc[g_rowptr[v] + ofs] = src[e];
    }
}

// ---------------- weight conversion: W [K][N] -> W^T [N][K] bf16 hi/lo ----------------
__global__ void wconvert(const float* W0, const float* W1, const float* W2,
                         const float* W3, const float* W4, const float* W5) {
    int idx = blockIdx.x * 256 + threadIdx.x;
    if (idx >= 6 * DIM * DIM) return;
    int layer = idx >> 14;
    int r = idx & 16383;
    int n = r >> 7, k = r & 127;
    const float* Ws[6] = {W0, W1, W2, W3, W4, W5};
    float val = Ws[layer][k * DIM + n];
    unsigned short hi, lo;
    split_bf(val, hi, lo);
    g_Whi[idx] = hi;   // layer*16384 + n*128 + k
    g_Wlo[idx] = lo;
}

// ---------------- aggregation: one warp per destination node, 4x unrolled ----------------
// OUT_BF16=1: write bf16 hi/lo row-major (GEMM input). Else fp32 to ext_out.
template <int SRC_NORM, int DST_NORM, int OUT_BF16>
__global__ void aggregate_kernel(const float* __restrict__ ext_in, int in_sel,
                                 float* __restrict__ ext_out) {
    const float* hin = (in_sel == 0) ? g_h[0] : (in_sel == 1) ? g_h[1] : ext_in;

    int v = (blockIdx.x * blockDim.x + threadIdx.x) >> 5;
    if (v >= N_NODES) return;
    int lane = threadIdx.x & 31;

    int beg = g_rowptr[v];
    int end = g_rowptr[v + 1];

    const float4* h4 = (const float4*)hin;
    float4 acc = make_float4(0.f, 0.f, 0.f, 0.f);

    int i = beg;
    for (; i + 4 <= end; i += 4) {
        int s0 = g_csrsrc[i + 0];
        int s1 = g_csrsrc[i + 1];
        int s2 = g_csrsrc[i + 2];
        int s3 = g_csrsrc[i + 3];
        float w0 = SRC_NORM ? g_ns[s0] : 1.0f;
        float w1 = SRC_NORM ? g_ns[s1] : 1.0f;
        float w2 = SRC_NORM ? g_ns[s2] : 1.0f;
        float w3 = SRC_NORM ? g_ns[s3] : 1.0f;
        float4 v0 = h4[s0 * 32 + lane];
        float4 v1 = h4[s1 * 32 + lane];
        float4 v2 = h4[s2 * 32 + lane];
        float4 v3 = h4[s3 * 32 + lane];
        acc.x += w0 * v0.x; acc.y += w0 * v0.y; acc.z += w0 * v0.z; acc.w += w0 * v0.w;
        acc.x += w1 * v1.x; acc.y += w1 * v1.y; acc.z += w1 * v1.z; acc.w += w1 * v1.w;
        acc.x += w2 * v2.x; acc.y += w2 * v2.y; acc.z += w2 * v2.z; acc.w += w2 * v2.w;
        acc.x += w3 * v3.x; acc.y += w3 * v3.y; acc.z += w3 * v3.z; acc.w += w3 * v3.w;
    }
    for (; i < end; i++) {
        int s = g_csrsrc[i];
        float w = SRC_NORM ? g_ns[s] : 1.0f;
        float4 vv = h4[s * 32 + lane];
        acc.x += w * vv.x; acc.y += w * vv.y; acc.z += w * vv.z; acc.w += w * vv.w;
    }
    if (DST_NORM) {
        float sc = g_nd[v];
        acc.x *= sc; acc.y *= sc; acc.z *= sc; acc.w *= sc;
    }

    if (OUT_BF16) {
        unsigned short h0, h1, h2, h3, l0, l1, l2, l3;
        split_bf(acc.x, h0, l0); split_bf(acc.y, h1, l1);
        split_bf(acc.z, h2, l2); split_bf(acc.w, h3, l3);
        uint2 hv = make_uint2((uint32_t)h0 | ((uint32_t)h1 << 16),
                              (uint32_t)h2 | ((uint32_t)h3 << 16));
        uint2 lv = make_uint2((uint32_t)l0 | ((uint32_t)l1 << 16),
                              (uint32_t)l2 | ((uint32_t)l3 << 16));
        *(uint2*)&g_Ahi[(size_t)v * DIM + lane * 4] = hv;
        *(uint2*)&g_Alo[(size_t)v * DIM + lane * 4] = lv;
    } else {
        ((float4*)ext_out)[v * 32 + lane] = acc;
    }
}

// ---------------- tensor-core GEMM via mma.sync (bf16x2 split, 3 passes) ----------------
// g_h[out_buf][row] = relu(A[row] @ W + b) * (do_ps ? g_ns[row] : 1)
// CTA: 128 rows x 128 cols, 8 warps (4M x 2N), warp tile 32x64.
__global__ void __launch_bounds__(256, 1) gemm_mma(
    const float* __restrict__ b, int layer, int out_buf, int do_ps) {
    extern __shared__ __align__(16) unsigned short sm[];
    unsigned short* sAh = sm;
    unsigned short* sAl = sm + 128 * SA;
    unsigned short* sWh = sm + 2 * 128 * SA;
    unsigned short* sWl = sm + 3 * 128 * SA;

    int tid = threadIdx.x;
    const uint4* gAh = (const uint4*)(g_Ahi + (size_t)blockIdx.x * (128 * DIM));
    const uint4* gAl = (const uint4*)(g_Alo + (size_t)blockIdx.x * (128 * DIM));
    const uint4* gWh = (const uint4*)(g_Whi + (size_t)layer * (DIM * DIM));
    const uint4* gWl = (const uint4*)(g_Wlo + (size_t)layer * (DIM * DIM));

    // stage tiles: 2048 uint4 each (128 rows x 16 uint4), padded smem stride
#pragma unroll
    for (int it = 0; it < 8; it++) {
        int i = tid + it * 256;
        int r = i >> 4, c = (i & 15) << 3;
        *(uint4*)&sAh[r * SA + c] = gAh[i];
        *(uint4*)&sAl[r * SA + c] = gAl[i];
        *(uint4*)&sWh[r * SA + c] = gWh[i];
        *(uint4*)&sWl[r * SA + c] = gWl[i];
    }
    __syncthreads();

    int warp = tid >> 5, lane = tid & 31;
    int wm = warp & 3, wn = warp >> 2;           // 4 M-warps x 2 N-warps
    int bm = wm * 32, bn = wn * 64;
    int lr = lane >> 2, lc = (lane & 3) * 2;

    float acc[2][8][4];
#pragma unroll
    for (int mi = 0; mi < 2; mi++)
#pragma unroll
        for (int ni = 0; ni < 8; ni++)
#pragma unroll
            for (int q = 0; q < 4; q++) acc[mi][ni][q] = 0.f;

    const unsigned short* AP[3] = {sAh, sAh, sAl};
    const unsigned short* BP[3] = {sWh, sWl, sWh};

#pragma unroll
    for (int p = 0; p < 3; p++) {
        const unsigned short* A = AP[p];
        const unsigned short* B = BP[p];
#pragma unroll
        for (int k = 0; k < 8; k++) {
            int k0 = k * 16;
            uint32_t af[2][4], bf[8][2];
#pragma unroll
            for (int mi = 0; mi < 2; mi++) {
                int r = bm + mi * 16 + lr;
                af[mi][0] = *(const uint32_t*)&A[r * SA + k0 + lc];
                af[mi][1] = *(const uint32_t*)&A[(r + 8) * SA + k0 + lc];
                af[mi][2] = *(const uint32_t*)&A[r * SA + k0 + 8 + lc];
                af[mi][3] = *(const uint32_t*)&A[(r + 8) * SA + k0 + 8 + lc];
            }
#pragma unroll
            for (int ni = 0; ni < 8; ni++) {
                int cc = bn + ni * 8 + lr;
                bf[ni][0] = *(const uint32_t*)&B[cc * SA + k0 + lc];
                bf[ni][1] = *(const uint32_t*)&B[cc * SA + k0 + 8 + lc];
            }
#pragma unroll
            for (int mi = 0; mi < 2; mi++)
#pragma unroll
                for (int ni = 0; ni < 8; ni++)
                    mma16816(acc[mi][ni], af[mi], bf[ni]);
        }
    }

    float* C = g_h[out_buf];
#pragma unroll
    for (int mi = 0; mi < 2; mi++) {
        int r0 = blockIdx.x * 128 + bm + mi * 16 + lr;
        int r1 = r0 + 8;
        float ps0 = 1.f, ps1 = 1.f;
        if (do_ps) {
            if (r0 < N_NODES) ps0 = g_ns[r0];
            if (r1 < N_NODES) ps1 = g_ns[r1];
        }
#pragma unroll
        for (int ni = 0; ni < 8; ni++) {
            int col = bn + ni * 8 + lc;
            float2 bv = *(const float2*)&b[col];
            if (r0 < N_NODES) {
                float2 o;
                o.x = fmaxf(acc[mi][ni][0] + bv.x, 0.f) * ps0;
                o.y = fmaxf(acc[mi][ni][1] + bv.y, 0.f) * ps0;
                *(float2*)&C[(size_t)r0 * DIM + col] = o;
            }
            if (r1 < N_NODES) {
                float2 o;
                o.x = fmaxf(acc[mi][ni][2] + bv.x, 0.f) * ps1;
                o.y = fmaxf(acc[mi][ni][3] + bv.y, 0.f) * ps1;
                *(float2*)&C[(size_t)r1 * DIM + col] = o;
            }
        }
    }
}

// ---------------- pooling: sorted graph_id -> register accumulation ----------------
__global__ void pool_kernel(int buf, const int* __restrict__ gid) {
    const float* h = g_h[buf];
    int group = blockIdx.x * 2 + (threadIdx.x >> 7);
    int d = threadIdx.x & 127;
    int start = group * 128;
    if (start >= N_NODES) return;
    int end = min(start + 128, N_NODES);

    int cur = gid[start];
    float acc = 0.f;
    int cnt = 0;
    for (int n = start; n < end; n++) {
        int g = gid[n];
        if (g != cur) {
            atomicAdd(&g_pooled[cur * DIM + d], acc);
            if (d == 0) atomicAdd(&g_gcount[cur], cnt);
            acc = 0.f; cnt = 0; cur = g;
        }
        acc += h[n * DIM + d];
        cnt++;
    }
    atomicAdd(&g_pooled[cur * DIM + d], acc);
    if (d == 0) atomicAdd(&g_gcount[cur], cnt);
}

// ---------------- head MLP ----------------
__global__ void mlp_kernel(const float* __restrict__ Wa, const float* __restrict__ ba,
                           const float* __restrict__ Wb, const float* __restrict__ bb,
                           float* __restrict__ out) {
    __shared__ float pm[N_GRAPHS * DIM];
    __shared__ float z[N_GRAPHS * HID];
    int t = threadIdx.x;

    for (int i = t; i < N_GRAPHS * DIM; i += 256) {
        int g = i / DIM;
        float cnt = fmaxf((float)g_gcount[g], 1.0f);
        pm[i] = g_pooled[i] / cnt;
    }
    __syncthreads();

    for (int i = t; i < N_GRAPHS * HID; i += 256) {
        int g = i / HID, j = i % HID;
        float s = ba[j];
        for (int d = 0; d < DIM; d++) s += pm[g * DIM + d] * Wa[d * HID + j];
        z[i] = fmaxf(s, 0.0f);
    }
    __syncthreads();

    for (int i = t; i < N_GRAPHS * N_CLASS; i += 256) {
        int g = i / N_CLASS, c = i % N_CLASS;
        float s = bb[c];
        for (int j = 0; j < HID; j++) s += z[g * HID + j] * Wb[j * N_CLASS + c];
        out[i] = s;
    }
}

// ---------------- launch ----------------
extern "C" void kernel_launch(void* const* d_in, const int* in_sizes, int n_in,
                              void* d_out, int out_size) {
    const float* feat = (const float*)d_in[0];
    const int* src = (const int*)d_in[1];
    const int* dst = (const int*)d_in[2];
    const int* gid = (const int*)d_in[3];
    const float* Ws[6] = {(const float*)d_in[4], (const float*)d_in[6], (const float*)d_in[8],
                          (const float*)d_in[10], (const float*)d_in[12], (const float*)d_in[14]};
    const float* bs[6] = {(const float*)d_in[5], (const float*)d_in[7], (const float*)d_in[9],
                          (const float*)d_in[11], (const float*)d_in[13], (const float*)d_in[15]};
    const float* Wa = (const float*)d_in[16];
    const float* ba = (const float*)d_in[17];
    const float* Wb = (const float*)d_in[18];
    const float* bb = (const float*)d_in[19];
    float* out = (float*)d_out;

    const int SMEM_DYN = 4 * 128 * SA * 2;   // 139264 B
    cudaFuncSetAttribute(gemm_mma, cudaFuncAttributeMaxDynamicSharedMemorySize, SMEM_DYN);

    // graph structure
    zero_kernel<<<SCAN_BLOCKS, 256>>>();
    degree_kernel<<<(N_EDGES + 255) / 256, 256>>>(src, dst);
    norm_kernel<<<SCAN_BLOCKS, 256>>>();
    scan_part1<<<SCAN_BLOCKS, 256>>>();
    scan_part2<<<1, 256>>>();
    scan_part3<<<SCAN_BLOCKS, 256>>>();
    fill_csr<<<(N_EDGES + 255) / 256, 256>>>(src, dst);
    wconvert<<<(6 * DIM * DIM + 255) / 256, 256>>>(Ws[0], Ws[1], Ws[2], Ws[3], Ws[4], Ws[5]);

    const int AGG_GRID = (N_NODES * 32 + 255) / 256;

    // Layer 0: per-edge src norm. GEMM epilogue pre-scales layers 0..4 by ns,
    // so layers 1..5 aggregate without per-edge norm loads. relu(x)*ns == relu(x*ns).
    aggregate_kernel<1, 1, 1><<<AGG_GRID, 256>>>(feat, -1, nullptr);
    gemm_mma<<<N_TILES, 256, SMEM_DYN>>>(bs[0], 0, 0, 1);

    for (int L = 1; L < 6; L++) {
        aggregate_kernel<0, 1, 1><<<AGG_GRID, 256>>>(nullptr, (L - 1) & 1, nullptr);
        gemm_mma<<<N_TILES, 256, SMEM_DYN>>>(bs[L], L, L & 1, (L < 5) ? 1 : 0);
    }
    // final features in g_h[1]

    pool_kernel<<<SCAN_BLOCKS, 256>>>(1, gid);
    mlp_kernel<<<1, 256>>>(Wa, ba, Wb, bb, out);

    // unnormalized aggregation h_agg [50000,128] (fp32 exact)
    aggregate_kernel<0, 0, 0><<<AGG_GRID, 256>>>(nullptr, 1, out + N_GRAPHS * N_CLASS);
}